// round 3
// baseline (speedup 1.0000x reference)
#include <cuda_runtime.h>
#include <cstdint>
#include <math_constants.h>

#define N_NODES 100000
#define N_EDGES 800000
#define DIM 64
#define HEADS 4
#define NCHUNK 98   // ceil(N_NODES/1024)

// ---------------- scratch (static __device__, no allocations) ----------------
__device__ float g_q[N_NODES * DIM];
__device__ float g_k[N_NODES * DIM];
__device__ float g_v[N_NODES * DIM];
__device__ float g_csr_att[N_EDGES * HEADS];     // raw logits -> exp(logit-m), CSR order
__device__ float g_dinv[N_NODES * HEADS];        // 1/(denom+eps)
__device__ int   g_src[N_EDGES];
__device__ int   g_dst[N_EDGES];
__device__ int   g_csr_src[N_EDGES];
__device__ int   g_csr_eid[N_EDGES];
__device__ int   g_deg[N_NODES];
__device__ int   g_rowptr[N_NODES + 1];
__device__ int   g_cursor[N_NODES];
__device__ int   g_chunksum[NCHUNK];
__device__ int   g_chunkoff[NCHUNK];
__device__ float g_zA[N_NODES * DIM];
__device__ float g_zB[N_NODES * DIM];
__device__ int   g_is64;

// ---------------- kernels ----------------

// detect whether edge_index is really int64 or silently int32 (JAX x64 off)
__global__ void k_detect(const long long* __restrict__ ei) {
    int ok = 1;
    for (int i = 0; i < 64; i++) {
        long long v = ei[i];
        if (v < 0 || v >= N_NODES) ok = 0;
    }
    g_is64 = ok;
}

__global__ void k_zero() {
    int i = blockIdx.x * blockDim.x + threadIdx.x;
    if (i < N_NODES) g_deg[i] = 0;
}

__global__ void k_prep(const long long* __restrict__ ei) {
    int i = blockIdx.x * blockDim.x + threadIdx.x;
    if (i >= N_EDGES) return;
    int s, d;
    if (g_is64) {
        s = (int)ei[i];
        d = (int)ei[N_EDGES + i];
    } else {
        const int* e32 = (const int*)ei;
        s = e32[i];
        d = e32[N_EDGES + i];
    }
    g_src[i] = s;
    g_dst[i] = d;
    atomicAdd(&g_deg[d], 1);
}

__global__ void k_chunksum() {
    __shared__ int sh[256];
    int b = blockIdx.x, t = threadIdx.x;
    int base = b * 1024;
    int sum = 0;
    for (int k = 0; k < 4; k++) {
        int i = base + k * 256 + t;
        if (i < N_NODES) sum += g_deg[i];
    }
    sh[t] = sum;
    __syncthreads();
    for (int off = 128; off; off >>= 1) {
        if (t < off) sh[t] += sh[t + off];
        __syncthreads();
    }
    if (t == 0) g_chunksum[b] = sh[0];
}

__global__ void k_scanmid() {
    int run = 0;
    for (int c = 0; c < NCHUNK; c++) {
        g_chunkoff[c] = run;
        run += g_chunksum[c];
    }
    g_rowptr[N_NODES] = run;
}

__global__ void k_scanchunk() {
    __shared__ int s[1024];
    int b = blockIdx.x, t = threadIdx.x;
    int i = b * 1024 + t;
    int v = (i < N_NODES) ? g_deg[i] : 0;
    s[t] = v;
    __syncthreads();
    for (int off = 1; off < 1024; off <<= 1) {
        int add = (t >= off) ? s[t - off] : 0;
        __syncthreads();
        s[t] += add;
        __syncthreads();
    }
    if (i < N_NODES) {
        int ex = g_chunkoff[b] + s[t] - v;   // exclusive prefix
        g_rowptr[i] = ex;
        g_cursor[i] = ex;
    }
}

__global__ void k_scatter() {
    int e = blockIdx.x * blockDim.x + threadIdx.x;
    if (e >= N_EDGES) return;
    int dst = g_dst[e];
    int p = atomicAdd(&g_cursor[dst], 1);
    g_csr_src[p] = g_src[e];
    g_csr_eid[p] = e;
}

// q/k/v projections: 32 rows per block, register-blocked (8 rows/thread-group)
__global__ void k_qkv(const float* __restrict__ x, const float* __restrict__ Wq,
                      const float* __restrict__ Wk, const float* __restrict__ Wv) {
    __shared__ float xs[32][64];
    int n0 = blockIdx.x * 32;
    int t = threadIdx.x;
    for (int k = 0; k < 8; k++) {
        int L = k * 256 + t;
        xs[L >> 6][L & 63] = x[n0 * 64 + L];
    }
    __syncthreads();
    int col = t & 63, rg = t >> 6;
    float aq[8] = {0}, ak[8] = {0}, av[8] = {0};
#pragma unroll 4
    for (int j = 0; j < 64; j++) {
        float wq = Wq[j * 64 + col];
        float wk = Wk[j * 64 + col];
        float wv = Wv[j * 64 + col];
#pragma unroll
        for (int r = 0; r < 8; r++) {
            float xv = xs[rg * 8 + r][j];
            aq[r] += xv * wq;
            ak[r] += xv * wk;
            av[r] += xv * wv;
        }
    }
#pragma unroll
    for (int r = 0; r < 8; r++) {
        int n = n0 + rg * 8 + r;
        g_q[n * 64 + col] = aq[r];
        g_k[n * 64 + col] = ak[r];
        g_v[n * 64 + col] = av[r];
    }
}

// Fused per-node attention: on-the-fly p = We-contracted q[dst], per-edge
// logits via width-8 butterfly, local segment softmax (no atomics, no extra
// global passes). Warp per node; lane = (h = lane>>3, g = lane&7).
// lane owns: p[h][g*8 .. g*8+8), qk dims d = g*2, g*2+1 of head h.
__global__ void k_node(const float* __restrict__ ea, const float* __restrict__ We) {
    int gid = blockIdx.x * blockDim.x + threadIdx.x;
    int node = gid >> 5;
    if (node >= N_NODES) return;
    int lane = gid & 31, h = lane >> 3, g = lane & 7;

    // q values for this head (broadcast within the 8-lane group via L1)
    const float4* q4 = (const float4*)(g_q + node * 64 + h * 16);
    float4 qa = q4[0], qb = q4[1], qc = q4[2], qd = q4[3];
    // the two q components this lane contributes to the q.k dot
    float2 qv2 = *(const float2*)(g_q + node * 64 + h * 16 + g * 2);

    // p_reg[jj] = sum_d We[(g*8+jj)*64 + h*16 + d] * q[node,h,d]
    float p_reg[8];
#pragma unroll
    for (int jj = 0; jj < 8; jj++) {
        const float4* w4 = (const float4*)(We + (g * 8 + jj) * 64 + h * 16);
        float4 w0 = w4[0], w1 = w4[1], w2 = w4[2], w3 = w4[3];
        p_reg[jj] = w0.x * qa.x + w0.y * qa.y + w0.z * qa.z + w0.w * qa.w
                  + w1.x * qb.x + w1.y * qb.y + w1.z * qb.z + w1.w * qb.w
                  + w2.x * qc.x + w2.y * qc.y + w2.z * qc.z + w2.w * qc.w
                  + w3.x * qd.x + w3.y * qd.y + w3.z * qd.z + w3.w * qd.w;
    }

    int beg = g_rowptr[node], end = g_rowptr[node + 1];
    float m = -CUDART_INF_F;
    for (int i = beg; i < end; i++) {
        int src = g_csr_src[i];
        int eid = g_csr_eid[i];
        const float4* e4 = (const float4*)(ea + (size_t)eid * 64 + g * 8);
        float4 e0 = e4[0], e1 = e4[1];
        float2 kv = *(const float2*)(g_k + src * 64 + h * 16 + g * 2);
        float part = e0.x * p_reg[0] + e0.y * p_reg[1] + e0.z * p_reg[2] + e0.w * p_reg[3]
                   + e1.x * p_reg[4] + e1.y * p_reg[5] + e1.z * p_reg[6] + e1.w * p_reg[7]
                   + qv2.x * kv.x + qv2.y * kv.y;
        part += __shfl_xor_sync(0xFFFFFFFFu, part, 1);
        part += __shfl_xor_sync(0xFFFFFFFFu, part, 2);
        part += __shfl_xor_sync(0xFFFFFFFFu, part, 4);
        float logit = part * 0.25f;   // 1/sqrt(16)
        if (g == 0) {
            g_csr_att[i * 4 + h] = logit;
            m = fmaxf(m, logit);
        }
    }
    if (g == 0) {
        float sum = 0.0f;
        for (int i = beg; i < end; i++) {
            float a = __expf(g_csr_att[i * 4 + h] - m);
            g_csr_att[i * 4 + h] = a;   // unnormalized; k_prop applies 1/denom
            sum += a;
        }
        g_dinv[node * 4 + h] = 1.0f / (sum + 1e-16f);
    }
}

// propagation: warp per node, pure gather. Normalization folded in via g_dinv.
// iter==7 fuses the final relu + residual and writes to out.
__global__ void k_prop(int iter, const float* __restrict__ x, float* __restrict__ out) {
    int gid = blockIdx.x * blockDim.x + threadIdx.x;
    int node = gid >> 5;
    if (node >= N_NODES) return;
    int lane = gid & 31;
    const float* zold = (iter == 0) ? g_v : ((iter & 1) ? g_zA : g_zB);
    float* znew = (iter & 1) ? g_zB : g_zA;
    int beg = g_rowptr[node], end = g_rowptr[node + 1];
    int h = lane >> 3;
    float inv = g_dinv[node * 4 + h];
    float ax = 0.0f, ay = 0.0f;
    for (int i = beg; i < end; i++) {
        int s = g_csr_src[i];
        float a = g_csr_att[i * 4 + h];
        float2 z = *(const float2*)(zold + s * 64 + lane * 2);
        ax += a * z.x;
        ay += a * z.y;
    }
    float2 vv = *(const float2*)(g_v + node * 64 + lane * 2);
    float ox = 0.1f * vv.x + 0.9f * (ax * inv);
    float oy = 0.1f * vv.y + 0.9f * (ay * inv);
    if (iter == 7) {
        float2 xv = *(const float2*)(x + node * 64 + lane * 2);
        float2 o;
        o.x = xv.x + fmaxf(ox, 0.0f);
        o.y = xv.y + fmaxf(oy, 0.0f);
        *(float2*)(out + node * 64 + lane * 2) = o;
    } else {
        float2 o; o.x = ox; o.y = oy;
        *(float2*)(znew + node * 64 + lane * 2) = o;
    }
}

// ---------------- launch ----------------
extern "C" void kernel_launch(void* const* d_in, const int* in_sizes, int n_in,
                              void* d_out, int out_size) {
    const float*     x  = (const float*)d_in[0];
    const long long* ei = (const long long*)d_in[1];
    const float*     ea = (const float*)d_in[2];
    const float*     Wq = (const float*)d_in[3];
    const float*     Wk = (const float*)d_in[4];
    const float*     Wv = (const float*)d_in[5];
    const float*     We = (const float*)d_in[6];
    float* out = (float*)d_out;

    k_detect<<<1, 1>>>(ei);
    k_zero<<<(N_NODES + 255) / 256, 256>>>();
    k_prep<<<(N_EDGES + 255) / 256, 256>>>(ei);
    k_chunksum<<<NCHUNK, 256>>>();
    k_scanmid<<<1, 1>>>();
    k_scanchunk<<<NCHUNK, 1024>>>();
    k_scatter<<<(N_EDGES + 255) / 256, 256>>>();
    k_qkv<<<N_NODES / 32, 256>>>(x, Wq, Wk, Wv);
    k_node<<<(N_NODES * 32 + 255) / 256, 256>>>(ea, We);
    for (int it = 0; it < 8; it++)
        k_prop<<<(N_NODES * 32 + 255) / 256, 256>>>(it, x, out);
}